// round 17
// baseline (speedup 1.0000x reference)
#include <cuda_runtime.h>
#include <cstdint>
#include <cstddef>

// ---------------------------------------------------------------------------
// Spiking conv + WTA, Round 17: SINGLE-PASS 151-row delta^2 grid.
// All event rows s+1+n are provably in [2,150] -> no clamps, no dump row,
// no segmasks, no pass overlap: exactly one fill + 180 scatter visits +
// one unbroken cumsum. Single-warp CTA per (b,ox,oy); lane = channel.
//   r(tau) = tau/16 - (3/32) relu(tau-16w) + (1/32) relu(tau-48w)   (exact)
// ---------------------------------------------------------------------------

#define COUT   32
#define W18    18
#define KS     48
#define TIN    100
#define TOUT   149
#define NSPAT  31
#define THETA  5.4f
#define GROWS  151         // rows 0..150; events land in [2,150]
#define CNTSZ  160         // ramp array; indices 102..159 provably zero
#define NROWS  (16 * 2 * 64 * 64)
#define NB_BIN (NROWS / 8) // binarize blocks: 8 input rows per block

// event tables, layout [w][o]
__device__ float4   g_t1[W18 * COUT];    // canonical event values v0..v3
__device__ uint4    g_off[W18 * COUT];   // pre-scaled row offsets n_i*128 (bytes)
__device__ unsigned g_bits[NROWS * 4];   // spike bitmasks, 2 MB

// merged prep: blocks [0, NB_BIN) binarize spikes (8 rows = 3200 B contiguous
// per block, float4 loads, smem atomicOr bit assembly — order-independent);
// blocks >= NB_BIN build the event tables (concurrent with binarize).
__global__ __launch_bounds__(256)
void prep_kernel(const float* __restrict__ xin, const float* __restrict__ weight) {
    if (blockIdx.x < NB_BIN) {
        __shared__ unsigned sm[32];        // 8 rows x 4 words
        int tid = threadIdx.x;
        if (tid < 32) sm[tid] = 0u;
        __syncthreads();
        if (tid < 200) {                   // 200 float4 = 800 floats = 8 rows
            float4 v = __ldg((const float4*)(xin + (size_t)blockIdx.x * 800) + tid);
            int id = tid * 4;
            float vv[4] = {v.x, v.y, v.z, v.w};
#pragma unroll
            for (int j = 0; j < 4; ++j) {
                int idx = id + j;
                int row = idx / 100;
                int t   = idx - row * 100;
                if (vv[j] != 0.f)
                    atomicOr(&sm[(row << 2) + (t >> 5)], 1u << (t & 31));
            }
        }
        __syncthreads();
        if (tid < 32) g_bits[(size_t)blockIdx.x * 32 + tid] = sm[tid];
    } else {
        int idx = (int)(blockIdx.x - NB_BIN) * 256 + threadIdx.x;
        if (idx >= W18 * COUT) return;
        int o = idx & 31;
        int w = idx >> 5;
        double wv = (double)weight[o * W18 + w];

        double p1 = 16.0 * wv;  int n1 = (int)floor(p1) + 1;  double f1 = (double)n1 - p1;
        double p2 = 48.0 * wv;  int n2 = (int)floor(p2) + 1;  double f2 = (double)n2 - p2;
        const double c1 = -3.0 / 32.0, c2 = 1.0 / 32.0;
        double e0 = c1 * f1, e1 = c1 * (1.0 - f1);
        double e2 = c2 * f2, e3 = c2 * (1.0 - f2);

        // canonical quad: strictly increasing distinct rows (merge collisions)
        int r0, r1, r2, r3; double v0, v1, v2, v3;
        if (n2 - n1 >= 2)      { r0=n1; r1=n1+1; r2=n2;   r3=n2+1; v0=e0;    v1=e1;    v2=e2;  v3=e3;  }
        else if (n2 == n1 + 1) { r0=n1; r1=n1+1; r2=n1+2; r3=n1+3; v0=e0;    v1=e1+e2; v2=e3;  v3=0.0; }
        else                   { r0=n1; r1=n1+1; r2=n1+2; r3=n1+3; v0=e0+e2; v1=e1+e3; v2=0.0; v3=0.0; }

        g_t1[idx]  = make_float4((float)v0, (float)v1, (float)v2, (float)v3);
        g_off[idx] = make_uint4((unsigned)(r0 * 128), (unsigned)(r1 * 128),
                                (unsigned)(r2 * 128), (unsigned)(r3 * 128));
    }
}

__global__ __launch_bounds__(32)
void wta_kernel(float* __restrict__ out) {
    __shared__ float4                 s_grid4[GROWS * COUT / 4]; // 19328 B
    __shared__ float                  s_cnt[CNTSZ];              // ramp d2
    __shared__ __align__(16) unsigned s_bits[72];                // 18 rows x 4

    float* s_grid = (float*)s_grid4;

    const int lane = threadIdx.x;
    const int bx   = blockIdx.x;                     // n = ox*31 + oy
    const int b    = blockIdx.y;
    const int ox   = bx / NSPAT;
    const int oy   = bx - ox * NSPAT;

    // ---- stage 1: fetch 18 bitmask rows (one LDG.128 per active lane) ----
    if (lane < W18) {
        int i = lane / 9, rem = lane - i * 9, kx = rem / 3, ky = rem - kx * 3;
        size_t rowidx = (((size_t)b * 2 + i) * 64 + (2 * ox + kx)) * 64 + (2 * oy + ky);
        uint4 v = __ldg((const uint4*)&g_bits[rowidx * 4]);
        *(uint4*)&s_bits[lane * 4] = v;
    }
#pragma unroll
    for (int i = lane; i < CNTSZ; i += 32) s_cnt[i] = 0.f;
    __syncwarp();

    // ---- stage 1b: shared-ramp counts: cnt[s+2] = (#spikes at s)/16 ----
#pragma unroll
    for (int seg = 0; seg < 4; ++seg) {
        int c = 0;
#pragma unroll
        for (int w = 0; w < W18; ++w) c += (int)((s_bits[w * 4 + seg] >> lane) & 1u);
        int s = seg * 32 + lane;
        if (s < TIN) s_cnt[s + 2] = (float)c * 0.0625f;
    }
    __syncwarp();

    // ---- FILL grid row r with its ramp value cnt[r] (clamp-free) ----
#pragma unroll
    for (int i = lane; i < GROWS * COUT / 4; i += 32) {
        float c = s_cnt[i >> 3];                     // 8 float4 per row
        s_grid4[i] = make_float4(c, c, c, c);
    }
    __syncwarp();

    // u32 shared-space base addresses for the scatter RMWs
    const uint32_t colb = (uint32_t)__cvta_generic_to_shared(s_grid) + (uint32_t)lane * 4u;

    // ---- scatter canonical event quads (no clamps: rows in [2,150]) ----
#pragma unroll 2
    for (int w = 0; w < W18; ++w) {
        float4 ev = __ldg(&g_t1[w * 32 + lane]);
        uint4  of = __ldg(&g_off[w * 32 + lane]);
        const uint32_t A0 = colb + of.x;
        const uint32_t A1 = colb + of.y;
        const uint32_t A2 = colb + of.z;
        const uint32_t A3 = colb + of.w;
        uint4 mw = *(const uint4*)&s_bits[w * 4];    // one LDS.128
        unsigned mm[4] = { mw.x, mw.y, mw.z, mw.w };
#pragma unroll
        for (int seg = 0; seg < 4; ++seg) {
            unsigned m = mm[seg];
            int sbase = seg * 32 + 1;                // r = s+1 for bit 0
            while (m) {
                int bp = __ffs((int)m) - 1;
                m &= m - 1;
                uint32_t off = (uint32_t)((sbase + bp) << 7);
                uint32_t u0 = A0 + off;
                uint32_t u1 = A1 + off;
                uint32_t u2 = A2 + off;
                uint32_t u3 = A3 + off;
                float g0, g1, g2, g3;
                asm volatile("ld.shared.f32 %0,[%1];" : "=f"(g0) : "r"(u0));
                asm volatile("ld.shared.f32 %0,[%1];" : "=f"(g1) : "r"(u1));
                asm volatile("ld.shared.f32 %0,[%1];" : "=f"(g2) : "r"(u2));
                asm volatile("ld.shared.f32 %0,[%1];" : "=f"(g3) : "r"(u3));
                g0 += ev.x; g1 += ev.y; g2 += ev.z; g3 += ev.w;
                asm volatile("st.shared.f32 [%0],%1;" :: "r"(u0), "f"(g0));
                asm volatile("st.shared.f32 [%0],%1;" :: "r"(u1), "f"(g1));
                asm volatile("st.shared.f32 [%0],%1;" :: "r"(u2), "f"(g2));
                asm volatile("st.shared.f32 [%0],%1;" :: "r"(u3), "f"(g3));
            }
        }
    }
    __syncwarp();

    // ---- double cumsum + WTA over t = 0..148 (one unbroken loop) ----
    // burn-down refractory (no ballot), ballot-gated argmax otherwise.
    // Kahan compensation: corrected slope = a1 - c1.
    float a1 = 0.f, c1 = 0.f, a2 = 0.f;
    int dep = 0, k = 0;
    int wt0 = -1, wt1 = -1, wt2 = -1, wt3 = -1;
    int wc0 = 0, wc1 = 0, wc2 = 0, wc3 = 0;
    {
        int t = 0;
        float v = s_grid[lane];
#pragma unroll 1
        while (t < TOUT) {
            if (dep > 0) {
                int burn = dep < (TOUT - t) ? dep : (TOUT - t);
                dep -= burn;
#pragma unroll 1
                for (int j = 0; j < burn; ++j) {
                    float vn = s_grid[(t + 1) * 32 + lane];   // t+1 <= 149 < GROWS
                    float y  = v - c1;
                    float tt = a1 + y;
                    c1 = (tt - a1) - y;
                    a1 = tt;
                    a2 += (a1 - c1);
                    v = vn; ++t;
                }
                continue;
            }
            float vn = s_grid[(t + 1) * 32 + lane];
            float y  = v - c1;
            float tt = a1 + y;
            c1 = (tt - a1) - y;
            a1 = tt;
            a2 += (a1 - c1);
            unsigned fm = __ballot_sync(0xffffffffu, a2 > THETA);
            if (fm) {
                float bv = a2; int bi = lane;
#pragma unroll
                for (int off = 16; off; off >>= 1) {
                    float ov = __shfl_xor_sync(0xffffffffu, bv, off);
                    int   oi = __shfl_xor_sync(0xffffffffu, bi, off);
                    if (ov > bv || (ov == bv && oi < bi)) { bv = ov; bi = oi; }
                }
                if      (k == 0) { wt0 = t; wc0 = bi; }
                else if (k == 1) { wt1 = t; wc1 = bi; }
                else if (k == 2) { wt2 = t; wc2 = bi; }
                else             { wt3 = t; wc3 = bi; }
                ++k;
                dep = KS - 1;      // burns t+1..t+47; fireable again at t+48
            }
            v = vn; ++t;
        }
    }
    __syncwarp();

    // ---- output: unconditional zero-fill, then <=4 winner pokes ----
    float* obase0 = out + ((size_t)b * 32 * (NSPAT * NSPAT) + bx) * TOUT;
    const size_t ocstride = (size_t)(NSPAT * NSPAT) * TOUT;
#pragma unroll
    for (int q = 0; q < 5; ++q) {
        int t = q * 32 + lane;
        if (t < TOUT) {
            float* p = obase0 + t;
#pragma unroll 1
            for (int oc = 0; oc < 32; ++oc) { *p = 0.f; p += ocstride; }
        }
    }
    __syncwarp();    // memory-orders zero stores before winner pokes
    if (lane < k) {
        int wt = (lane == 0) ? wt0 : (lane == 1) ? wt1 : (lane == 2) ? wt2 : wt3;
        int wc = (lane == 0) ? wc0 : (lane == 1) ? wc1 : (lane == 2) ? wc2 : wc3;
        obase0[(size_t)wc * ocstride + wt] = 1.0f;
    }
}

extern "C" void kernel_launch(void* const* d_in, const int* in_sizes, int n_in,
                              void* d_out, int out_size) {
    const float* spikes = (const float*)d_in[0];
    const float* weight = (const float*)d_in[1];
    if (n_in >= 2 && in_sizes[0] == 576) {     // defensive input identification
        spikes = (const float*)d_in[1];
        weight = (const float*)d_in[0];
    }

    prep_kernel<<<NB_BIN + 3, 256>>>(spikes, weight);

    dim3 grid(NSPAT * NSPAT, 16);   // (n, batch)
    wta_kernel<<<grid, 32>>>((float*)d_out);
}